// round 4
// baseline (speedup 1.0000x reference)
#include <cuda_runtime.h>
#include <math.h>

#define B_TOTAL 16384
#define PI_F 3.14159265358979323846f

// ---------------- scratch (static device globals; no allocation) ----------------
__device__ float g_ang[10 * 16];       // per-class angles table
__device__ float g_cpost[10 * 32];     // per-class cpost table
__device__ int   g_cls[B_TOTAL];       // class id per sample
__device__ float g_qf[B_TOTAL * 256];  // quantum features (B, G*64)

__device__ __forceinline__ float lrelu(float x) { return x > 0.f ? x : 0.2f * x; }

// ---------------- Kernel A1: per-class tables (labels are one-hot) ----------------
__global__ void tables_kernel(const float* __restrict__ W1, const float* __restrict__ b1,
                              const float* __restrict__ W2, const float* __restrict__ b2,
                              const float* __restrict__ Wa, const float* __restrict__ ba,
                              const float* __restrict__ Wp1, const float* __restrict__ bp1,
                              const float* __restrict__ Wp2, const float* __restrict__ bp2)
{
    __shared__ float h[64], p1[32];
    int t = threadIdx.x;
    for (int c = 0; c < 10; c++) {
        float hv = 0.f;
        if (t < 64) { hv = lrelu(W1[t * 10 + c] + b1[t]); h[t] = hv; }
        __syncthreads();
        float acc = 0.f;
        if (t < 64) {
            acc = b2[t];
            for (int k = 0; k < 64; k++) acc = fmaf(W2[t * 64 + k], h[k], acc);
            acc = lrelu(acc);
        }
        __syncthreads();
        if (t < 64) h[t] = hv + acc;
        if (t < 32) p1[t] = lrelu(Wp1[t * 10 + c] + bp1[t]);
        __syncthreads();
        if (t < 16) {
            float a = ba[t];
            for (int k = 0; k < 64; k++) a = fmaf(Wa[t * 64 + k], h[k], a);
            g_ang[c * 16 + t] = tanhf(a) * PI_F;
        }
        if (t < 32) {
            float a = bp2[t];
            for (int k = 0; k < 32; k++) a = fmaf(Wp2[t * 32 + k], p1[k], a);
            g_cpost[c * 32 + t] = lrelu(a);
        }
        __syncthreads();
    }
}

// ---------------- Kernel A2: class id per sample ----------------
__global__ void class_kernel(const float* __restrict__ labels)
{
    int b = blockIdx.x * 256 + threadIdx.x;
    const float* l = labels + b * 10;
    int c = 0; float best = l[0];
#pragma unroll
    for (int j = 1; j < 10; j++) { float v = l[j]; if (v > best) { best = v; c = j; } }
    g_cls[b] = c;
}

// ---------------- Kernel B: quantum simulation (warp per sample, 4 gens) ----------------
// Amp index idx = lane*8 + j. Wire w <-> bit (7-w) of idx.
// Wires 0..4 -> lane bits (mask 16>>w), wires 5..7 -> local bits 2,1,0 of j.
__global__ __launch_bounds__(256) void qsim_kernel(const float* __restrict__ noise,
                                                   const float* __restrict__ qp)
{
    __shared__ float2 cs[192];            // cos/sin of 0.5*w for 4 gens x 48 gates
    __shared__ float  psi[8][8][2][2];    // [warp][qubit][basis][re/im]
    int tid = threadIdx.x;
    if (tid < 192) {
        float w = qp[tid];
        float sw, cw; sincosf(0.5f * w, &sw, &cw);
        cs[tid] = make_float2(cw, sw);
    }
    int warp = tid >> 5, lane = tid & 31;
    int b = blockIdx.x * 8 + warp;
    __syncthreads();
    int c = g_cls[b];
    if (lane < 8) {
        // RZ(theta) * RY(ang + noise) |0>
        float t = 0.5f * (g_ang[c * 16 + lane] + noise[b * 8 + lane]);
        float st, ct; sincosf(t, &st, &ct);
        float th = 0.5f * g_ang[c * 16 + 8 + lane];
        float sth, cth; sincosf(th, &sth, &cth);
        psi[warp][lane][0][0] = ct * cth;
        psi[warp][lane][0][1] = -ct * sth;
        psi[warp][lane][1][0] = st * cth;
        psi[warp][lane][1][1] = st * sth;
    }
    __syncwarp();

    // base product over wires 0..4 (lane bits)
    float br = 1.f, bi = 0.f;
#pragma unroll
    for (int k = 0; k < 5; k++) {
        int bit = (lane >> (4 - k)) & 1;
        float pr = psi[warp][k][bit][0], pi = psi[warp][k][bit][1];
        float nr = br * pr - bi * pi;
        float ni = br * pi + bi * pr;
        br = nr; bi = ni;
    }
    // q[b6*2+b7] = psi6[b6]*psi7[b7]
    float qr[4], qi[4];
#pragma unroll
    for (int b6 = 0; b6 < 2; b6++)
#pragma unroll
        for (int b7 = 0; b7 < 2; b7++) {
            float xr = psi[warp][6][b6][0], xi = psi[warp][6][b6][1];
            float yr = psi[warp][7][b7][0], yi = psi[warp][7][b7][1];
            qr[b6 * 2 + b7] = xr * yr - xi * yi;
            qi[b6 * 2 + b7] = xr * yi + xi * yr;
        }
    // fold base into psi5
    float b5r[2], b5i[2];
#pragma unroll
    for (int b5 = 0; b5 < 2; b5++) {
        float pr = psi[warp][5][b5][0], pi = psi[warp][5][b5][1];
        b5r[b5] = br * pr - bi * pi;
        b5i[b5] = br * pi + bi * pr;
    }
    float ar[8], ai[8], sflip[8];
#pragma unroll
    for (int j = 0; j < 8; j++) {
        int b5 = (j >> 2) & 1, q67 = j & 3;
        ar[j] = b5r[b5] * qr[q67] - b5i[b5] * qi[q67];
        ai[j] = b5r[b5] * qi[q67] + b5i[b5] * qr[q67];
        int idx = lane * 8 + j;
        sflip[j] = (__popc(idx & (idx >> 1) & 0x7F) & 1) ? -1.f : 1.f;  // fused CZ chain sign
    }

    for (int g = 0; g < 4; g++) {
        float re[8], im[8];
#pragma unroll
        for (int j = 0; j < 8; j++) { re[j] = ar[j]; im[j] = ai[j]; }

        for (int d = 0; d < 6; d++) {
            const float2* csd = &cs[g * 48 + d * 8];
            // wires 0..4: cross-lane
            for (int w = 0; w < 5; w++) {
                float2 csv = csd[w];
                int m = 16 >> w;
                float cg = csv.x;
                float sg = (lane & m) ? csv.y : -csv.y;
#pragma unroll
                for (int j = 0; j < 8; j++) {
                    float orr = __shfl_xor_sync(0xffffffffu, re[j], m);
                    float oii = __shfl_xor_sync(0xffffffffu, im[j], m);
                    re[j] = fmaf(sg, orr, cg * re[j]);
                    im[j] = fmaf(sg, oii, cg * im[j]);
                }
            }
            // wire 5: local bit 2 (pairs j, j+4)
            {
                float2 csv = csd[5]; float c_ = csv.x, s_ = csv.y;
#pragma unroll
                for (int j0 = 0; j0 < 4; j0++) {
                    int j1 = j0 + 4;
                    float r0 = re[j0], i0 = im[j0], r1 = re[j1], i1 = im[j1];
                    re[j0] = fmaf(-s_, r1, c_ * r0); im[j0] = fmaf(-s_, i1, c_ * i0);
                    re[j1] = fmaf(s_, r0, c_ * r1);  im[j1] = fmaf(s_, i0, c_ * i1);
                }
            }
            // wire 6: local bit 1 (pairs j, j+2)
            {
                float2 csv = csd[6]; float c_ = csv.x, s_ = csv.y;
#pragma unroll
                for (int jj = 0; jj < 4; jj++) {
                    int j0 = (jj & 1) | ((jj & 2) << 1);  // 0,1,4,5
                    int j1 = j0 + 2;
                    float r0 = re[j0], i0 = im[j0], r1 = re[j1], i1 = im[j1];
                    re[j0] = fmaf(-s_, r1, c_ * r0); im[j0] = fmaf(-s_, i1, c_ * i0);
                    re[j1] = fmaf(s_, r0, c_ * r1);  im[j1] = fmaf(s_, i0, c_ * i1);
                }
            }
            // wire 7: local bit 0 (pairs j, j+1)
            {
                float2 csv = csd[7]; float c_ = csv.x, s_ = csv.y;
#pragma unroll
                for (int j0 = 0; j0 < 8; j0 += 2) {
                    int j1 = j0 + 1;
                    float r0 = re[j0], i0 = im[j0], r1 = re[j1], i1 = im[j1];
                    re[j0] = fmaf(-s_, r1, c_ * r0); im[j0] = fmaf(-s_, i1, c_ * i0);
                    re[j1] = fmaf(s_, r0, c_ * r1);  im[j1] = fmaf(s_, i0, c_ * i1);
                }
            }
            // fused CZ chain (diagonal signs)
#pragma unroll
            for (int j = 0; j < 8; j++) { re[j] *= sflip[j]; im[j] *= sflip[j]; }
        }

        // epilogue: probs[:64]/max(probs[:64]) (global sum cancels)
        float p[8];
#pragma unroll
        for (int j = 0; j < 8; j++) p[j] = re[j] * re[j] + im[j] * im[j];
        float mx = p[0];
#pragma unroll
        for (int j = 1; j < 8; j++) mx = fmaxf(mx, p[j]);
        mx = fmaxf(mx, __shfl_xor_sync(0xffffffffu, mx, 4));
        mx = fmaxf(mx, __shfl_xor_sync(0xffffffffu, mx, 2));
        mx = fmaxf(mx, __shfl_xor_sync(0xffffffffu, mx, 1));
        if (lane < 8) {
            float inv = 1.f / mx;
            float* dst = &g_qf[b * 256 + g * 64 + lane * 8];
            float4 v0 = make_float4(p[0] * inv, p[1] * inv, p[2] * inv, p[3] * inv);
            float4 v1 = make_float4(p[4] * inv, p[5] * inv, p[6] * inv, p[7] * inv);
            *(float4*)dst = v0;
            *(float4*)(dst + 4) = v1;
        }
    }
}

// ---------------- Kernel C: fused MLP 288->128(LN)->128(LN)->64 tanh ----------------
#define XS_STRIDE 292
#define H_STRIDE  132
#define SMEM_C ((32 * XS_STRIDE + 32 * H_STRIDE + 8192) * 4)

__global__ __launch_bounds__(256) void mlp_kernel(
    const float* __restrict__ Wq1, const float* __restrict__ bq1,
    const float* __restrict__ g1,  const float* __restrict__ be1,
    const float* __restrict__ Wq2, const float* __restrict__ bq2,
    const float* __restrict__ g2,  const float* __restrict__ be2,
    const float* __restrict__ Wq3, const float* __restrict__ bq3,
    float* __restrict__ out)
{
    extern __shared__ float sm[];
    float* xs = sm;                         // 32 x 292
    float* h1 = sm + 32 * XS_STRIDE;        // 32 x 132
    float* wc = h1 + 32 * H_STRIDE;         // 8192 floats weight chunk
    int tid = threadIdx.x, warp = tid >> 5, lane = tid & 31;
    int b0 = blockIdx.x * 32;

    // stage x = [qf(256) | cpost(32)]
    for (int i = tid; i < 32 * 256; i += 256) {
        int s = i >> 8, k = i & 255;
        xs[s * XS_STRIDE + k] = g_qf[(b0 + s) * 256 + k];
    }
    for (int i = tid; i < 32 * 32; i += 256) {
        int s = i >> 5, k = i & 31;
        xs[s * XS_STRIDE + 256 + k] = g_cpost[g_cls[b0 + s] * 32 + k];
    }

    int ob = warp * 16;
    // ---- layer 1: 288 -> 128 ----
    float acc[16];
#pragma unroll
    for (int i = 0; i < 16; i++) acc[i] = bq1[ob + i];
    for (int ch = 0; ch < 6; ch++) {
        __syncthreads();
        for (int i = tid * 4; i < 128 * 48; i += 1024) {
            int o = i / 48, kk = i % 48;
            *(float4*)&wc[i] = *(const float4*)&Wq1[o * 288 + ch * 48 + kk];
        }
        __syncthreads();
        const float* xr = &xs[lane * XS_STRIDE + ch * 48];
#pragma unroll
        for (int kk = 0; kk < 48; kk += 4) {
            float4 xv = *(const float4*)&xr[kk];
#pragma unroll
            for (int i = 0; i < 16; i++) {
                float4 wv = *(const float4*)&wc[(ob + i) * 48 + kk];
                acc[i] = fmaf(xv.x, wv.x, acc[i]);
                acc[i] = fmaf(xv.y, wv.y, acc[i]);
                acc[i] = fmaf(xv.z, wv.z, acc[i]);
                acc[i] = fmaf(xv.w, wv.w, acc[i]);
            }
        }
    }
    __syncthreads();
#pragma unroll
    for (int i = 0; i < 16; i += 4) {
        float4 v = make_float4(lrelu(acc[i]), lrelu(acc[i + 1]), lrelu(acc[i + 2]), lrelu(acc[i + 3]));
        *(float4*)&h1[lane * H_STRIDE + ob + i] = v;
    }
    __syncthreads();

    // ---- LN1 (warp handles 4 samples) ----
    {
        float gv[4], bev[4];
#pragma unroll
        for (int r = 0; r < 4; r++) { gv[r] = g1[lane + 32 * r]; bev[r] = be1[lane + 32 * r]; }
        int s0 = warp * 4;
        for (int s = s0; s < s0 + 4; s++) {
            float v[4]; float sum = 0.f, sq = 0.f;
#pragma unroll
            for (int r = 0; r < 4; r++) {
                v[r] = h1[s * H_STRIDE + lane + 32 * r];
                sum += v[r]; sq = fmaf(v[r], v[r], sq);
            }
#pragma unroll
            for (int off = 16; off; off >>= 1) {
                sum += __shfl_xor_sync(0xffffffffu, sum, off);
                sq  += __shfl_xor_sync(0xffffffffu, sq, off);
            }
            float mu = sum * (1.f / 128.f);
            float var = sq * (1.f / 128.f) - mu * mu;
            float rs = rsqrtf(var + 1e-5f);
#pragma unroll
            for (int r = 0; r < 4; r++)
                h1[s * H_STRIDE + lane + 32 * r] = (v[r] - mu) * rs * gv[r] + bev[r];
        }
    }
    __syncthreads();

    // ---- layer 2: 128 -> 128 ----
    float* h2 = xs;  // reuse xs region, stride H_STRIDE
    float a2[16];
#pragma unroll
    for (int i = 0; i < 16; i++) a2[i] = bq2[ob + i];
    for (int ch = 0; ch < 2; ch++) {
        __syncthreads();
        for (int i = tid * 4; i < 128 * 64; i += 1024) {
            int o = i >> 6, kk = i & 63;
            *(float4*)&wc[i] = *(const float4*)&Wq2[o * 128 + ch * 64 + kk];
        }
        __syncthreads();
        const float* xr = &h1[lane * H_STRIDE + ch * 64];
#pragma unroll
        for (int kk = 0; kk < 64; kk += 4) {
            float4 xv = *(const float4*)&xr[kk];
#pragma unroll
            for (int i = 0; i < 16; i++) {
                float4 wv = *(const float4*)&wc[(ob + i) * 64 + kk];
                a2[i] = fmaf(xv.x, wv.x, a2[i]);
                a2[i] = fmaf(xv.y, wv.y, a2[i]);
                a2[i] = fmaf(xv.z, wv.z, a2[i]);
                a2[i] = fmaf(xv.w, wv.w, a2[i]);
            }
        }
    }
    __syncthreads();
#pragma unroll
    for (int i = 0; i < 16; i += 4) {
        float4 v = make_float4(lrelu(a2[i]), lrelu(a2[i + 1]), lrelu(a2[i + 2]), lrelu(a2[i + 3]));
        *(float4*)&h2[lane * H_STRIDE + ob + i] = v;
    }
    __syncthreads();

    // ---- LN2 ----
    {
        float gv[4], bev[4];
#pragma unroll
        for (int r = 0; r < 4; r++) { gv[r] = g2[lane + 32 * r]; bev[r] = be2[lane + 32 * r]; }
        int s0 = warp * 4;
        for (int s = s0; s < s0 + 4; s++) {
            float v[4]; float sum = 0.f, sq = 0.f;
#pragma unroll
            for (int r = 0; r < 4; r++) {
                v[r] = h2[s * H_STRIDE + lane + 32 * r];
                sum += v[r]; sq = fmaf(v[r], v[r], sq);
            }
#pragma unroll
            for (int off = 16; off; off >>= 1) {
                sum += __shfl_xor_sync(0xffffffffu, sum, off);
                sq  += __shfl_xor_sync(0xffffffffu, sq, off);
            }
            float mu = sum * (1.f / 128.f);
            float var = sq * (1.f / 128.f) - mu * mu;
            float rs = rsqrtf(var + 1e-5f);
#pragma unroll
            for (int r = 0; r < 4; r++)
                h2[s * H_STRIDE + lane + 32 * r] = (v[r] - mu) * rs * gv[r] + bev[r];
        }
    }
    __syncthreads();

    // ---- layer 3: 128 -> 64, tanh ----
    int ob3 = warp * 8;
    float a3[8];
#pragma unroll
    for (int i = 0; i < 8; i++) a3[i] = bq3[ob3 + i];
    for (int i = tid * 4; i < 64 * 128; i += 1024)
        *(float4*)&wc[i] = *(const float4*)&Wq3[i];
    __syncthreads();
    {
        const float* xr = &h2[lane * H_STRIDE];
#pragma unroll
        for (int kk = 0; kk < 128; kk += 4) {
            float4 xv = *(const float4*)&xr[kk];
#pragma unroll
            for (int i = 0; i < 8; i++) {
                float4 wv = *(const float4*)&wc[(ob3 + i) * 128 + kk];
                a3[i] = fmaf(xv.x, wv.x, a3[i]);
                a3[i] = fmaf(xv.y, wv.y, a3[i]);
                a3[i] = fmaf(xv.z, wv.z, a3[i]);
                a3[i] = fmaf(xv.w, wv.w, a3[i]);
            }
        }
    }
    __syncthreads();
    float* ot = wc;  // reuse as 32 x 65 output staging
#pragma unroll
    for (int i = 0; i < 8; i++) ot[lane * 65 + ob3 + i] = tanhf(a3[i]);
    __syncthreads();
    for (int i = tid; i < 32 * 64; i += 256) {
        int s = i >> 6, o = i & 63;
        out[(b0 + s) * 64 + o] = ot[s * 65 + o];
    }
}

// ---------------- launch ----------------
extern "C" void kernel_launch(void* const* d_in, const int* in_sizes, int n_in,
                              void* d_out, int out_size)
{
    const float* noise  = (const float*)d_in[0];
    const float* labels = (const float*)d_in[1];
    const float* qp     = (const float*)d_in[2];
    const float* W1  = (const float*)d_in[3];
    const float* b1  = (const float*)d_in[4];
    const float* W2  = (const float*)d_in[5];
    const float* b2  = (const float*)d_in[6];
    const float* Wa  = (const float*)d_in[7];
    const float* ba  = (const float*)d_in[8];
    const float* Wp1 = (const float*)d_in[9];
    const float* bp1 = (const float*)d_in[10];
    const float* Wp2 = (const float*)d_in[11];
    const float* bp2 = (const float*)d_in[12];
    const float* Wq1 = (const float*)d_in[13];
    const float* bq1 = (const float*)d_in[14];
    const float* g1  = (const float*)d_in[15];
    const float* be1 = (const float*)d_in[16];
    const float* Wq2 = (const float*)d_in[17];
    const float* bq2 = (const float*)d_in[18];
    const float* g2  = (const float*)d_in[19];
    const float* be2 = (const float*)d_in[20];
    const float* Wq3 = (const float*)d_in[21];
    const float* bq3 = (const float*)d_in[22];

    tables_kernel<<<1, 64>>>(W1, b1, W2, b2, Wa, ba, Wp1, bp1, Wp2, bp2);
    class_kernel<<<64, 256>>>(labels);
    qsim_kernel<<<2048, 256>>>(noise, qp);

    cudaFuncSetAttribute(mlp_kernel, cudaFuncAttributeMaxDynamicSharedMemorySize, SMEM_C);
    mlp_kernel<<<512, 256, SMEM_C>>>(Wq1, bq1, g1, be1, Wq2, bq2, g2, be2, Wq3, bq3,
                                     (float*)d_out);
}

// round 5
// speedup vs baseline: 1.1503x; 1.1503x over previous
#include <cuda_runtime.h>
#include <math.h>

#define B_TOTAL 16384
#define PI_F 3.14159265358979323846f

typedef unsigned long long u64;

// ---------------- packed f32x2 helpers (Blackwell 2xFP32 pipe, exact fp32) ----------------
__device__ __forceinline__ u64 pk(float lo, float hi) {
    u64 d; asm("mov.b64 %0, {%1, %2};" : "=l"(d) : "f"(lo), "f"(hi)); return d;
}
__device__ __forceinline__ void upk(u64 v, float& lo, float& hi) {
    asm("mov.b64 {%0, %1}, %2;" : "=f"(lo), "=f"(hi) : "l"(v));
}
__device__ __forceinline__ u64 f2fma(u64 a, u64 b, u64 c) {
    u64 d; asm("fma.rn.f32x2 %0, %1, %2, %3;" : "=l"(d) : "l"(a), "l"(b), "l"(c)); return d;
}
__device__ __forceinline__ u64 f2mul(u64 a, u64 b) {
    u64 d; asm("mul.rn.f32x2 %0, %1, %2;" : "=l"(d) : "l"(a), "l"(b)); return d;
}

// ---------------- scratch (static device globals; no allocation) ----------------
__device__ float g_ang[10 * 16];       // per-class angles table
__device__ float g_cpost[10 * 32];     // per-class cpost table
__device__ int   g_cls[B_TOTAL];       // class id per sample
__device__ float g_qf[B_TOTAL * 256];  // quantum features (B, G*64)

__device__ __forceinline__ float lrelu(float x) { return x > 0.f ? x : 0.2f * x; }

// ---------------- Kernel A1: per-class tables (labels are one-hot) ----------------
__global__ void tables_kernel(const float* __restrict__ W1, const float* __restrict__ b1,
                              const float* __restrict__ W2, const float* __restrict__ b2,
                              const float* __restrict__ Wa, const float* __restrict__ ba,
                              const float* __restrict__ Wp1, const float* __restrict__ bp1,
                              const float* __restrict__ Wp2, const float* __restrict__ bp2)
{
    __shared__ float h[64], p1[32];
    int t = threadIdx.x;
    for (int c = 0; c < 10; c++) {
        float hv = 0.f;
        if (t < 64) { hv = lrelu(W1[t * 10 + c] + b1[t]); h[t] = hv; }
        __syncthreads();
        float acc = 0.f;
        if (t < 64) {
            acc = b2[t];
            for (int k = 0; k < 64; k++) acc = fmaf(W2[t * 64 + k], h[k], acc);
            acc = lrelu(acc);
        }
        __syncthreads();
        if (t < 64) h[t] = hv + acc;
        if (t < 32) p1[t] = lrelu(Wp1[t * 10 + c] + bp1[t]);
        __syncthreads();
        if (t < 16) {
            float a = ba[t];
            for (int k = 0; k < 64; k++) a = fmaf(Wa[t * 64 + k], h[k], a);
            g_ang[c * 16 + t] = tanhf(a) * PI_F;
        }
        if (t < 32) {
            float a = bp2[t];
            for (int k = 0; k < 32; k++) a = fmaf(Wp2[t * 32 + k], p1[k], a);
            g_cpost[c * 32 + t] = lrelu(a);
        }
        __syncthreads();
    }
}

// ---------------- Kernel A2: class id per sample ----------------
__global__ void class_kernel(const float* __restrict__ labels)
{
    int b = blockIdx.x * 256 + threadIdx.x;
    const float* l = labels + b * 10;
    int c = 0; float best = l[0];
#pragma unroll
    for (int j = 1; j < 10; j++) { float v = l[j]; if (v > best) { best = v; c = j; } }
    g_cls[b] = c;
}

// ---------------- Kernel B: quantum simulation (warp per sample, 4 gens) ----------------
// Amp index idx = lane*8 + j. Wire w <-> bit (7-w) of idx.
// Wires 0..4 -> lane bits (mask 16>>w), wires 5..7 -> local bits 2,1,0 of j.
// Each amplitude (re,im) lives packed in one 64-bit register; rotations use f32x2 FMA.
__global__ __launch_bounds__(256) void qsim_kernel(const float* __restrict__ noise,
                                                   const float* __restrict__ qp)
{
    __shared__ float2 cs[192];            // cos/sin of 0.5*w for 4 gens x 48 gates
    __shared__ float  psi[8][8][2][2];    // [warp][qubit][basis][re/im]
    int tid = threadIdx.x;
    if (tid < 192) {
        float w = qp[tid];
        float sw, cw; sincosf(0.5f * w, &sw, &cw);
        cs[tid] = make_float2(cw, sw);
    }
    int warp = tid >> 5, lane = tid & 31;
    int b = blockIdx.x * 8 + warp;
    __syncthreads();
    int c = g_cls[b];
    if (lane < 8) {
        // RZ(theta) * RY(ang + noise) |0>
        float t = 0.5f * (g_ang[c * 16 + lane] + noise[b * 8 + lane]);
        float st, ct; sincosf(t, &st, &ct);
        float th = 0.5f * g_ang[c * 16 + 8 + lane];
        float sth, cth; sincosf(th, &sth, &cth);
        psi[warp][lane][0][0] = ct * cth;
        psi[warp][lane][0][1] = -ct * sth;
        psi[warp][lane][1][0] = st * cth;
        psi[warp][lane][1][1] = st * sth;
    }
    __syncwarp();

    // base product over wires 0..4 (lane bits)
    float br = 1.f, bi = 0.f;
#pragma unroll
    for (int k = 0; k < 5; k++) {
        int bit = (lane >> (4 - k)) & 1;
        float pr = psi[warp][k][bit][0], pi = psi[warp][k][bit][1];
        float nr = br * pr - bi * pi;
        float ni = br * pi + bi * pr;
        br = nr; bi = ni;
    }
    float qr[4], qi[4];
#pragma unroll
    for (int b6 = 0; b6 < 2; b6++)
#pragma unroll
        for (int b7 = 0; b7 < 2; b7++) {
            float xr = psi[warp][6][b6][0], xi = psi[warp][6][b6][1];
            float yr = psi[warp][7][b7][0], yi = psi[warp][7][b7][1];
            qr[b6 * 2 + b7] = xr * yr - xi * yi;
            qi[b6 * 2 + b7] = xr * yi + xi * yr;
        }
    float b5r[2], b5i[2];
#pragma unroll
    for (int b5 = 0; b5 < 2; b5++) {
        float pr = psi[warp][5][b5][0], pi = psi[warp][5][b5][1];
        b5r[b5] = br * pr - bi * pi;
        b5i[b5] = br * pi + bi * pr;
    }
    u64 amp0[8], sfp[8];
#pragma unroll
    for (int j = 0; j < 8; j++) {
        int b5 = (j >> 2) & 1, q67 = j & 3;
        float arj = b5r[b5] * qr[q67] - b5i[b5] * qi[q67];
        float aij = b5r[b5] * qi[q67] + b5i[b5] * qr[q67];
        amp0[j] = pk(arj, aij);
        int idx = lane * 8 + j;
        float sf = (__popc(idx & (idx >> 1) & 0x7F) & 1) ? -1.f : 1.f;  // fused CZ chain
        sfp[j] = pk(sf, sf);
    }

    for (int g = 0; g < 4; g++) {
        u64 a[8];
#pragma unroll
        for (int j = 0; j < 8; j++) a[j] = amp0[j];

        for (int d = 0; d < 6; d++) {
            const float2* csd = &cs[g * 48 + d * 8];
            // wires 0..4: cross-lane (2x SHFL + 1 mul.f32x2 + 1 fma.f32x2 per amp)
            for (int w = 0; w < 5; w++) {
                float2 csv = csd[w];
                int m = 16 >> w;
                u64 cgp = pk(csv.x, csv.x);
                float sg = (lane & m) ? csv.y : -csv.y;
                u64 sgp = pk(sg, sg);
#pragma unroll
                for (int j = 0; j < 8; j++) {
                    u64 part = __shfl_xor_sync(0xffffffffu, a[j], m);
                    a[j] = f2fma(sgp, part, f2mul(cgp, a[j]));
                }
            }
            // wire 5: local bit 2 (pairs j, j+4)
            {
                float2 csv = csd[5];
                u64 cp = pk(csv.x, csv.x), sp = pk(csv.y, csv.y), msp = pk(-csv.y, -csv.y);
#pragma unroll
                for (int j0 = 0; j0 < 4; j0++) {
                    int j1 = j0 + 4;
                    u64 v0 = a[j0], v1 = a[j1];
                    a[j0] = f2fma(msp, v1, f2mul(cp, v0));
                    a[j1] = f2fma(sp, v0, f2mul(cp, v1));
                }
            }
            // wire 6: local bit 1 (pairs j, j+2)
            {
                float2 csv = csd[6];
                u64 cp = pk(csv.x, csv.x), sp = pk(csv.y, csv.y), msp = pk(-csv.y, -csv.y);
#pragma unroll
                for (int jj = 0; jj < 4; jj++) {
                    int j0 = (jj & 1) | ((jj & 2) << 1);  // 0,1,4,5
                    int j1 = j0 + 2;
                    u64 v0 = a[j0], v1 = a[j1];
                    a[j0] = f2fma(msp, v1, f2mul(cp, v0));
                    a[j1] = f2fma(sp, v0, f2mul(cp, v1));
                }
            }
            // wire 7: local bit 0 (pairs j, j+1)
            {
                float2 csv = csd[7];
                u64 cp = pk(csv.x, csv.x), sp = pk(csv.y, csv.y), msp = pk(-csv.y, -csv.y);
#pragma unroll
                for (int j0 = 0; j0 < 8; j0 += 2) {
                    int j1 = j0 + 1;
                    u64 v0 = a[j0], v1 = a[j1];
                    a[j0] = f2fma(msp, v1, f2mul(cp, v0));
                    a[j1] = f2fma(sp, v0, f2mul(cp, v1));
                }
            }
            // fused CZ chain (diagonal signs), packed
#pragma unroll
            for (int j = 0; j < 8; j++) a[j] = f2mul(a[j], sfp[j]);
        }

        // epilogue: probs[:64]/max(probs[:64]) (global sum cancels)
        float p[8];
#pragma unroll
        for (int j = 0; j < 8; j++) {
            float r, i; upk(a[j], r, i);
            p[j] = fmaf(r, r, i * i);
        }
        float mx = p[0];
#pragma unroll
        for (int j = 1; j < 8; j++) mx = fmaxf(mx, p[j]);
        mx = fmaxf(mx, __shfl_xor_sync(0xffffffffu, mx, 4));
        mx = fmaxf(mx, __shfl_xor_sync(0xffffffffu, mx, 2));
        mx = fmaxf(mx, __shfl_xor_sync(0xffffffffu, mx, 1));
        if (lane < 8) {
            float inv = 1.f / mx;
            float* dst = &g_qf[b * 256 + g * 64 + lane * 8];
            float4 v0 = make_float4(p[0] * inv, p[1] * inv, p[2] * inv, p[3] * inv);
            float4 v1 = make_float4(p[4] * inv, p[5] * inv, p[6] * inv, p[7] * inv);
            *(float4*)dst = v0;
            *(float4*)(dst + 4) = v1;
        }
    }
}

// ---------------- Kernel C: fused MLP 288->128(LN)->128(LN)->64 tanh ----------------
// 64 samples/CTA, 2 samples per thread, f32x2 even/odd-k partial sums.
#define XS_STRIDE 292
#define H_STRIDE  132
#define NS 64
#define SMEM_C ((NS * XS_STRIDE + NS * H_STRIDE + 8192) * 4)

__global__ __launch_bounds__(256) void mlp_kernel(
    const float* __restrict__ Wq1, const float* __restrict__ bq1,
    const float* __restrict__ g1,  const float* __restrict__ be1,
    const float* __restrict__ Wq2, const float* __restrict__ bq2,
    const float* __restrict__ g2,  const float* __restrict__ be2,
    const float* __restrict__ Wq3, const float* __restrict__ bq3,
    float* __restrict__ out)
{
    extern __shared__ float sm[];
    float* xs = sm;                         // 64 x 292 (also reused as h2, stride 132)
    float* h1 = sm + NS * XS_STRIDE;        // 64 x 132
    float* wc = h1 + NS * H_STRIDE;         // 8192-float weight chunk
    int tid = threadIdx.x, warp = tid >> 5, lane = tid & 31;
    int b0 = blockIdx.x * NS;
    int s1 = lane, s2 = lane + 32;

    // stage x = [qf(256) | cpost(32)] for 64 samples
    for (int i = tid; i < NS * 64; i += 256) {
        int s = i >> 6, k4 = (i & 63) << 2;
        *(float4*)&xs[s * XS_STRIDE + k4] = *(const float4*)&g_qf[(b0 + s) * 256 + k4];
    }
    for (int i = tid; i < NS * 8; i += 256) {
        int s = i >> 3, k4 = (i & 7) << 2;
        *(float4*)&xs[s * XS_STRIDE + 256 + k4] = *(const float4*)&g_cpost[g_cls[b0 + s] * 32 + k4];
    }

    int ob = warp * 16;
    // ---- layer 1: 288 -> 128 ----
    u64 aA[16], aB[16];
#pragma unroll
    for (int i = 0; i < 16; i++) { float bv = bq1[ob + i]; aA[i] = pk(bv, 0.f); aB[i] = pk(bv, 0.f); }
    for (int ch = 0; ch < 6; ch++) {
        __syncthreads();
        for (int i = tid * 4; i < 128 * 48; i += 1024) {
            int o = i / 48, kk = i % 48;
            *(float4*)&wc[i] = *(const float4*)&Wq1[o * 288 + ch * 48 + kk];
        }
        __syncthreads();
        const ulonglong2* xrA = (const ulonglong2*)&xs[s1 * XS_STRIDE + ch * 48];
        const ulonglong2* xrB = (const ulonglong2*)&xs[s2 * XS_STRIDE + ch * 48];
#pragma unroll
        for (int kk = 0; kk < 12; kk++) {
            ulonglong2 xa = xrA[kk], xb = xrB[kk];
#pragma unroll
            for (int i = 0; i < 16; i++) {
                ulonglong2 w = ((const ulonglong2*)&wc[(ob + i) * 48])[kk];
                aA[i] = f2fma(w.x, xa.x, aA[i]);
                aA[i] = f2fma(w.y, xa.y, aA[i]);
                aB[i] = f2fma(w.x, xb.x, aB[i]);
                aB[i] = f2fma(w.y, xb.y, aB[i]);
            }
        }
    }
    __syncthreads();
#pragma unroll
    for (int i = 0; i < 16; i++) {
        float lo, hi;
        upk(aA[i], lo, hi); h1[s1 * H_STRIDE + ob + i] = lrelu(lo + hi);
        upk(aB[i], lo, hi); h1[s2 * H_STRIDE + ob + i] = lrelu(lo + hi);
    }
    __syncthreads();

    // ---- LN1 (warp handles 8 samples) ----
    {
        float gv[4], bev[4];
#pragma unroll
        for (int r = 0; r < 4; r++) { gv[r] = g1[lane + 32 * r]; bev[r] = be1[lane + 32 * r]; }
        int s0 = warp * 8;
        for (int s = s0; s < s0 + 8; s++) {
            float v[4]; float sum = 0.f, sq = 0.f;
#pragma unroll
            for (int r = 0; r < 4; r++) {
                v[r] = h1[s * H_STRIDE + lane + 32 * r];
                sum += v[r]; sq = fmaf(v[r], v[r], sq);
            }
#pragma unroll
            for (int off = 16; off; off >>= 1) {
                sum += __shfl_xor_sync(0xffffffffu, sum, off);
                sq  += __shfl_xor_sync(0xffffffffu, sq, off);
            }
            float mu = sum * (1.f / 128.f);
            float var = sq * (1.f / 128.f) - mu * mu;
            float rs = rsqrtf(var + 1e-5f);
#pragma unroll
            for (int r = 0; r < 4; r++)
                h1[s * H_STRIDE + lane + 32 * r] = (v[r] - mu) * rs * gv[r] + bev[r];
        }
    }
    __syncthreads();

    // ---- layer 2: 128 -> 128 ----
    float* h2 = xs;  // reuse, stride H_STRIDE
#pragma unroll
    for (int i = 0; i < 16; i++) { float bv = bq2[ob + i]; aA[i] = pk(bv, 0.f); aB[i] = pk(bv, 0.f); }
    for (int ch = 0; ch < 2; ch++) {
        __syncthreads();
        for (int i = tid * 4; i < 128 * 64; i += 1024) {
            int o = i >> 6, kk = i & 63;
            *(float4*)&wc[i] = *(const float4*)&Wq2[o * 128 + ch * 64 + kk];
        }
        __syncthreads();
        const ulonglong2* xrA = (const ulonglong2*)&h1[s1 * H_STRIDE + ch * 64];
        const ulonglong2* xrB = (const ulonglong2*)&h1[s2 * H_STRIDE + ch * 64];
#pragma unroll
        for (int kk = 0; kk < 16; kk++) {
            ulonglong2 xa = xrA[kk], xb = xrB[kk];
#pragma unroll
            for (int i = 0; i < 16; i++) {
                ulonglong2 w = ((const ulonglong2*)&wc[(ob + i) * 64])[kk];
                aA[i] = f2fma(w.x, xa.x, aA[i]);
                aA[i] = f2fma(w.y, xa.y, aA[i]);
                aB[i] = f2fma(w.x, xb.x, aB[i]);
                aB[i] = f2fma(w.y, xb.y, aB[i]);
            }
        }
    }
    __syncthreads();
#pragma unroll
    for (int i = 0; i < 16; i++) {
        float lo, hi;
        upk(aA[i], lo, hi); h2[s1 * H_STRIDE + ob + i] = lrelu(lo + hi);
        upk(aB[i], lo, hi); h2[s2 * H_STRIDE + ob + i] = lrelu(lo + hi);
    }
    __syncthreads();

    // ---- LN2 ----
    {
        float gv[4], bev[4];
#pragma unroll
        for (int r = 0; r < 4; r++) { gv[r] = g2[lane + 32 * r]; bev[r] = be2[lane + 32 * r]; }
        int s0 = warp * 8;
        for (int s = s0; s < s0 + 8; s++) {
            float v[4]; float sum = 0.f, sq = 0.f;
#pragma unroll
            for (int r = 0; r < 4; r++) {
                v[r] = h2[s * H_STRIDE + lane + 32 * r];
                sum += v[r]; sq = fmaf(v[r], v[r], sq);
            }
#pragma unroll
            for (int off = 16; off; off >>= 1) {
                sum += __shfl_xor_sync(0xffffffffu, sum, off);
                sq  += __shfl_xor_sync(0xffffffffu, sq, off);
            }
            float mu = sum * (1.f / 128.f);
            float var = sq * (1.f / 128.f) - mu * mu;
            float rs = rsqrtf(var + 1e-5f);
#pragma unroll
            for (int r = 0; r < 4; r++)
                h2[s * H_STRIDE + lane + 32 * r] = (v[r] - mu) * rs * gv[r] + bev[r];
        }
    }

    // ---- layer 3: 128 -> 64, tanh ----
    int ob3 = warp * 8;
    u64 cA[8], cB[8];
#pragma unroll
    for (int i = 0; i < 8; i++) { float bv = bq3[ob3 + i]; cA[i] = pk(bv, 0.f); cB[i] = pk(bv, 0.f); }
    __syncthreads();
    for (int i = tid * 4; i < 64 * 128; i += 1024)
        *(float4*)&wc[i] = *(const float4*)&Wq3[i];
    __syncthreads();
    {
        const ulonglong2* xrA = (const ulonglong2*)&h2[s1 * H_STRIDE];
        const ulonglong2* xrB = (const ulonglong2*)&h2[s2 * H_STRIDE];
#pragma unroll
        for (int kk = 0; kk < 32; kk++) {
            ulonglong2 xa = xrA[kk], xb = xrB[kk];
#pragma unroll
            for (int i = 0; i < 8; i++) {
                ulonglong2 w = ((const ulonglong2*)&wc[(ob3 + i) * 128])[kk];
                cA[i] = f2fma(w.x, xa.x, cA[i]);
                cA[i] = f2fma(w.y, xa.y, cA[i]);
                cB[i] = f2fma(w.x, xb.x, cB[i]);
                cB[i] = f2fma(w.y, xb.y, cB[i]);
            }
        }
    }
    // direct stores: 2 x float4 per sample per thread
    {
        float oA[8], oB[8];
#pragma unroll
        for (int i = 0; i < 8; i++) {
            float lo, hi;
            upk(cA[i], lo, hi); oA[i] = tanhf(lo + hi);
            upk(cB[i], lo, hi); oB[i] = tanhf(lo + hi);
        }
        float* d1 = &out[(b0 + s1) * 64 + ob3];
        float* d2 = &out[(b0 + s2) * 64 + ob3];
        *(float4*)d1       = make_float4(oA[0], oA[1], oA[2], oA[3]);
        *(float4*)(d1 + 4) = make_float4(oA[4], oA[5], oA[6], oA[7]);
        *(float4*)d2       = make_float4(oB[0], oB[1], oB[2], oB[3]);
        *(float4*)(d2 + 4) = make_float4(oB[4], oB[5], oB[6], oB[7]);
    }
}

// ---------------- launch ----------------
extern "C" void kernel_launch(void* const* d_in, const int* in_sizes, int n_in,
                              void* d_out, int out_size)
{
    const float* noise  = (const float*)d_in[0];
    const float* labels = (const float*)d_in[1];
    const float* qp     = (const float*)d_in[2];
    const float* W1  = (const float*)d_in[3];
    const float* b1  = (const float*)d_in[4];
    const float* W2  = (const float*)d_in[5];
    const float* b2  = (const float*)d_in[6];
    const float* Wa  = (const float*)d_in[7];
    const float* ba  = (const float*)d_in[8];
    const float* Wp1 = (const float*)d_in[9];
    const float* bp1 = (const float*)d_in[10];
    const float* Wp2 = (const float*)d_in[11];
    const float* bp2 = (const float*)d_in[12];
    const float* Wq1 = (const float*)d_in[13];
    const float* bq1 = (const float*)d_in[14];
    const float* g1  = (const float*)d_in[15];
    const float* be1 = (const float*)d_in[16];
    const float* Wq2 = (const float*)d_in[17];
    const float* bq2 = (const float*)d_in[18];
    const float* g2  = (const float*)d_in[19];
    const float* be2 = (const float*)d_in[20];
    const float* Wq3 = (const float*)d_in[21];
    const float* bq3 = (const float*)d_in[22];

    tables_kernel<<<1, 64>>>(W1, b1, W2, b2, Wa, ba, Wp1, bp1, Wp2, bp2);
    class_kernel<<<64, 256>>>(labels);
    qsim_kernel<<<2048, 256>>>(noise, qp);

    cudaFuncSetAttribute(mlp_kernel, cudaFuncAttributeMaxDynamicSharedMemorySize, SMEM_C);
    mlp_kernel<<<256, 256, SMEM_C>>>(Wq1, bq1, g1, be1, Wq2, bq2, g2, be2, Wq3, bq3,
                                     (float*)d_out);
}